// round 1
// baseline (speedup 1.0000x reference)
#include <cuda_runtime.h>
#include <math.h>

// ---------------- model constants ----------------
#define C_DIM   1024
#define H_NUM   16
#define D_HEAD  64
#define L_NUM   8
#define T_SEQ   1024
#define B_SZ    2
#define M_ROWS  (B_SZ * T_SEQ)      // 2048
#define FF_DIM  4096
#define V_SZ    32000

// ---------------- device scratch ----------------
__device__ float g_x   [M_ROWS * C_DIM];        // residual stream
__device__ float g_h   [M_ROWS * C_DIM];        // LN output / attn output
__device__ float g_qkv [M_ROWS * 3 * C_DIM];    // fused qkv
__device__ float g_ff  [M_ROWS * FF_DIM];       // FF intermediate
__device__ float g_wp  [3 * C_DIM * C_DIM];     // packed qkv weights (per layer)

// ---------------- embedding ----------------
__global__ void k_embed(const int* __restrict__ idx,
                        const float* __restrict__ tok,
                        const float* __restrict__ pos,
                        float* __restrict__ x)
{
    int m = blockIdx.x;
    int c = threadIdx.x * 4;
    int t = m & (T_SEQ - 1);
    int v = idx[m];
    float4 a = *(const float4*)(tok + (size_t)v * C_DIM + c);
    float4 p = *(const float4*)(pos + (size_t)t * C_DIM + c);
    a.x += p.x; a.y += p.y; a.z += p.z; a.w += p.w;
    *(float4*)(x + (size_t)m * C_DIM + c) = a;
}

// ---------------- layernorm (one block per row, C=1024) ----------------
__global__ void k_ln(const float* __restrict__ x,
                     const float* __restrict__ sc,
                     const float* __restrict__ bi,
                     float* __restrict__ out)
{
    int m = blockIdx.x;
    int tid = threadIdx.x;                 // 256 threads
    int c = tid * 4;
    float4 v = *(const float4*)(x + (size_t)m * C_DIM + c);
    float s = v.x + v.y + v.z + v.w;
    float q = v.x*v.x + v.y*v.y + v.z*v.z + v.w*v.w;

    __shared__ float rs[8], rq[8];
#pragma unroll
    for (int o = 16; o > 0; o >>= 1) {
        s += __shfl_xor_sync(0xffffffffu, s, o);
        q += __shfl_xor_sync(0xffffffffu, q, o);
    }
    if ((tid & 31) == 0) { rs[tid >> 5] = s; rq[tid >> 5] = q; }
    __syncthreads();
    float sum = 0.f, sq = 0.f;
#pragma unroll
    for (int w = 0; w < 8; w++) { sum += rs[w]; sq += rq[w]; }

    float mu = sum * (1.0f / C_DIM);
    float var = sq * (1.0f / C_DIM) - mu * mu;
    float rstd = rsqrtf(var + 1e-5f);

    float4 svv = *(const float4*)(sc + c);
    float4 bvv = *(const float4*)(bi + c);
    float4 o;
    o.x = (v.x - mu) * rstd * svv.x + bvv.x;
    o.y = (v.y - mu) * rstd * svv.y + bvv.y;
    o.z = (v.z - mu) * rstd * svv.z + bvv.z;
    o.w = (v.w - mu) * rstd * svv.w + bvv.w;
    *(float4*)(out + (size_t)m * C_DIM + c) = o;
}

// ---------------- pack qkv weights: (L,H,C,D) -> (C, 3C) ----------------
__global__ void k_pack(const float* __restrict__ Wq,
                       const float* __restrict__ Wk,
                       const float* __restrict__ Wv,
                       float* __restrict__ out, int l)
{
    int i = blockIdx.x * 256 + threadIdx.x;    // i = k*3072 + n
    int n = i % 3072;
    int k = i / 3072;
    int s = n >> 10;
    int r = n & 1023;
    int hh = r >> 6;
    int d = r & 63;
    const float* W = (s == 0) ? Wq : ((s == 1) ? Wk : Wv);
    out[i] = W[(((size_t)l * H_NUM + hh) * C_DIM + k) * D_HEAD + d];
}

// ---------------- SGEMM 128x128x8, 256 threads, 8x8 micro-tile -------------
// C[M,N] = A[M,K] @ B  (+bias)(+relu)(+res)
// TRANSB=0: B is (K,N) row-major.  TRANSB=1: B is (N,K) row-major (computes A@B^T).
template<int TRANSB>
__global__ __launch_bounds__(256)
void sgemm(const float* __restrict__ A, const float* __restrict__ B,
           float* Cmat, const float* __restrict__ bias, const float* res,
           int M, int N, int K, int relu)
{
    __shared__ float As[8][132];
    __shared__ float Bs[8][132];
    int tid = threadIdx.x;
    int bm = blockIdx.y << 7;
    int bn = blockIdx.x << 7;
    int tx = tid & 15, ty = tid >> 4;

    float acc[8][8];
#pragma unroll
    for (int i = 0; i < 8; i++)
#pragma unroll
        for (int j = 0; j < 8; j++) acc[i][j] = 0.f;

    int arow = tid >> 1;
    int acol = (tid & 1) << 2;
    const float* Ap = A + (size_t)(bm + arow) * K + acol;

    for (int k0 = 0; k0 < K; k0 += 8) {
        float4 av = *(const float4*)(Ap + k0);
        As[acol + 0][arow] = av.x;
        As[acol + 1][arow] = av.y;
        As[acol + 2][arow] = av.z;
        As[acol + 3][arow] = av.w;
        if (TRANSB) {
            int bnr = tid >> 1;
            int bk  = (tid & 1) << 2;
            float4 bv = *(const float4*)(B + (size_t)(bn + bnr) * K + k0 + bk);
            Bs[bk + 0][bnr] = bv.x;
            Bs[bk + 1][bnr] = bv.y;
            Bs[bk + 2][bnr] = bv.z;
            Bs[bk + 3][bnr] = bv.w;
        } else {
            int bk   = tid >> 5;
            int bcol = (tid & 31) << 2;
            float4 bv = *(const float4*)(B + (size_t)(k0 + bk) * N + bn + bcol);
            *(float4*)&Bs[bk][bcol] = bv;
        }
        __syncthreads();
#pragma unroll
        for (int kk = 0; kk < 8; kk++) {
            float a[8], b[8];
            *(float4*)&a[0] = *(const float4*)&As[kk][ty << 3];
            *(float4*)&a[4] = *(const float4*)&As[kk][(ty << 3) + 4];
            *(float4*)&b[0] = *(const float4*)&Bs[kk][tx << 3];
            *(float4*)&b[4] = *(const float4*)&Bs[kk][(tx << 3) + 4];
#pragma unroll
            for (int i = 0; i < 8; i++)
#pragma unroll
                for (int j = 0; j < 8; j++)
                    acc[i][j] += a[i] * b[j];
        }
        __syncthreads();
    }

#pragma unroll
    for (int i = 0; i < 8; i++) {
        int row = bm + (ty << 3) + i;
#pragma unroll
        for (int j = 0; j < 8; j++) {
            int col = bn + (tx << 3) + j;
            float v = acc[i][j];
            if (bias) v += bias[col];
            if (relu) v = fmaxf(v, 0.f);
            if (res)  v += res[(size_t)row * N + col];
            Cmat[(size_t)row * N + col] = v;
        }
    }
}

// ---------------- causal flash attention ----------------
// grid: (T/64, B*H). Per block: 64 queries, loop 32-key tiles, online softmax.
__global__ __launch_bounds__(256)
void k_attn(const float* __restrict__ qkv, float* __restrict__ outb)
{
    __shared__ float qs[64][64];
    __shared__ float ks[32][65];
    __shared__ float vs[32][65];
    __shared__ float ps[64][33];

    int qt  = blockIdx.x;            // query tile 0..15
    int b   = blockIdx.y >> 4;
    int hh  = blockIdx.y & 15;
    int tid = threadIdx.x;
    int tx  = tid & 15, ty = tid >> 4;

    const float* qbase = qkv + (size_t)(b * T_SEQ + qt * 64) * 3072 + hh * 64;
#pragma unroll
    for (int e = 0; e < 16; e++) {
        int i = tid + e * 256;
        int r = i >> 6, d = i & 63;
        qs[r][d] = qbase[(size_t)r * 3072 + d] * 0.125f;   // 1/sqrt(64)
    }

    float m_r[4], l_r[4], oa[4][4];
#pragma unroll
    for (int i = 0; i < 4; i++) {
        m_r[i] = -1e30f; l_r[i] = 0.f;
#pragma unroll
        for (int j = 0; j < 4; j++) oa[i][j] = 0.f;
    }

    const float* kb = qkv + (size_t)(b * T_SEQ) * 3072 + 1024 + hh * 64;
    const float* vb = qkv + (size_t)(b * T_SEQ) * 3072 + 2048 + hh * 64;

    int nkt = 2 * qt + 2;
    for (int kt = 0; kt < nkt; kt++) {
        __syncthreads();   // prev O-gemm done reading ks/vs/ps; qs stores visible (1st iter)
#pragma unroll
        for (int e = 0; e < 8; e++) {
            int i = tid + e * 256;
            int r = i >> 6, d = i & 63;
            ks[r][d] = kb[(size_t)(kt * 32 + r) * 3072 + d];
            vs[r][d] = vb[(size_t)(kt * 32 + r) * 3072 + d];
        }
        __syncthreads();

        // S = q @ k^T : rows 4ty+i, cols 2tx+j
        float sv[4][2];
#pragma unroll
        for (int i = 0; i < 4; i++) { sv[i][0] = 0.f; sv[i][1] = 0.f; }
#pragma unroll 8
        for (int d = 0; d < 64; d++) {
            float b0 = ks[2 * tx + 0][d];
            float b1 = ks[2 * tx + 1][d];
#pragma unroll
            for (int i = 0; i < 4; i++) {
                float a = qs[4 * ty + i][d];
                sv[i][0] += a * b0;
                sv[i][1] += a * b1;
            }
        }

        // causal mask (only needed on the last two tiles)
        if (kt >= 2 * qt) {
#pragma unroll
            for (int i = 0; i < 4; i++)
#pragma unroll
                for (int j = 0; j < 2; j++) {
                    int sg = kt * 32 + 2 * tx + j;
                    int tg = qt * 64 + 4 * ty + i;
                    if (sg > tg) sv[i][j] = -1e30f;
                }
        }

        // online softmax per row (reduce over the 16 tx lanes)
#pragma unroll
        for (int i = 0; i < 4; i++) {
            float mloc = fmaxf(sv[i][0], sv[i][1]);
#pragma unroll
            for (int o = 8; o > 0; o >>= 1)
                mloc = fmaxf(mloc, __shfl_xor_sync(0xffffffffu, mloc, o));
            float mnew = fmaxf(m_r[i], mloc);
            float p0 = expf(sv[i][0] - mnew);
            float p1 = expf(sv[i][1] - mnew);
            float corr = expf(m_r[i] - mnew);
            float rsum = p0 + p1;
#pragma unroll
            for (int o = 8; o > 0; o >>= 1)
                rsum += __shfl_xor_sync(0xffffffffu, rsum, o);
            l_r[i] = l_r[i] * corr + rsum;
            m_r[i] = mnew;
            oa[i][0] *= corr; oa[i][1] *= corr; oa[i][2] *= corr; oa[i][3] *= corr;
            ps[4 * ty + i][2 * tx + 0] = p0;
            ps[4 * ty + i][2 * tx + 1] = p1;
        }
        __syncthreads();

        // O += P @ V : rows 4ty+i, d-cols 4tx+j
#pragma unroll 4
        for (int s = 0; s < 32; s++) {
            float b0 = vs[s][4 * tx + 0];
            float b1 = vs[s][4 * tx + 1];
            float b2 = vs[s][4 * tx + 2];
            float b3 = vs[s][4 * tx + 3];
#pragma unroll
            for (int i = 0; i < 4; i++) {
                float a = ps[4 * ty + i][s];
                oa[i][0] += a * b0;
                oa[i][1] += a * b1;
                oa[i][2] += a * b2;
                oa[i][3] += a * b3;
            }
        }
    }

    float* ob = outb + (size_t)(b * T_SEQ + qt * 64) * C_DIM + hh * 64;
#pragma unroll
    for (int i = 0; i < 4; i++) {
        float inv = 1.0f / l_r[i];
#pragma unroll
        for (int j = 0; j < 4; j++)
            ob[(size_t)(4 * ty + i) * C_DIM + 4 * tx + j] = oa[i][j] * inv;
    }
}

// ---------------- launcher ----------------
extern "C" void kernel_launch(void* const* d_in, const int* in_sizes, int n_in,
                              void* d_out, int out_size)
{
    const int*   idx    = (const int*)  d_in[0];
    const float* tok    = (const float*)d_in[1];
    const float* pos    = (const float*)d_in[2];
    const float* ln1_s  = (const float*)d_in[3];
    const float* ln1_b  = (const float*)d_in[4];
    const float* Wq     = (const float*)d_in[5];
    const float* Wk     = (const float*)d_in[6];
    const float* Wv     = (const float*)d_in[7];
    const float* Wo     = (const float*)d_in[8];
    const float* bo     = (const float*)d_in[9];
    const float* ln2_s  = (const float*)d_in[10];
    const float* ln2_b  = (const float*)d_in[11];
    const float* W1     = (const float*)d_in[12];
    const float* b1     = (const float*)d_in[13];
    const float* W2     = (const float*)d_in[14];
    const float* b2     = (const float*)d_in[15];
    const float* lnf_s  = (const float*)d_in[16];
    const float* lnf_b  = (const float*)d_in[17];
    float* out = (float*)d_out;

    float *x, *h, *qkv, *ff, *wp;
    cudaGetSymbolAddress((void**)&x,   g_x);
    cudaGetSymbolAddress((void**)&h,   g_h);
    cudaGetSymbolAddress((void**)&qkv, g_qkv);
    cudaGetSymbolAddress((void**)&ff,  g_ff);
    cudaGetSymbolAddress((void**)&wp,  g_wp);

    k_embed<<<M_ROWS, 256>>>(idx, tok, pos, x);

    for (int l = 0; l < L_NUM; l++) {
        // LN1
        k_ln<<<M_ROWS, 256>>>(x, ln1_s + l * C_DIM, ln1_b + l * C_DIM, h);
        // pack qkv weights for this layer
        k_pack<<<(3 * C_DIM * C_DIM) / 256, 256>>>(Wq, Wk, Wv, wp, l);
        // fused qkv GEMM: (2048,1024) @ (1024,3072)
        sgemm<0><<<dim3(3072 / 128, M_ROWS / 128), 256>>>(
            h, wp, qkv, nullptr, nullptr, M_ROWS, 3072, C_DIM, 0);
        // attention -> h
        k_attn<<<dim3(T_SEQ / 64, B_SZ * H_NUM), 256>>>(qkv, h);
        // x = x + h @ Wo + bo
        sgemm<0><<<dim3(C_DIM / 128, M_ROWS / 128), 256>>>(
            h, Wo + (size_t)l * C_DIM * C_DIM, x, bo + l * C_DIM, x,
            M_ROWS, C_DIM, C_DIM, 0);
        // LN2
        k_ln<<<M_ROWS, 256>>>(x, ln2_s + l * C_DIM, ln2_b + l * C_DIM, h);
        // ff = relu(h @ W1 + b1)
        sgemm<0><<<dim3(FF_DIM / 128, M_ROWS / 128), 256>>>(
            h, W1 + (size_t)l * C_DIM * FF_DIM, ff, b1 + l * FF_DIM, nullptr,
            M_ROWS, FF_DIM, C_DIM, 1);
        // x = x + ff @ W2 + b2
        sgemm<0><<<dim3(C_DIM / 128, M_ROWS / 128), 256>>>(
            ff, W2 + (size_t)l * FF_DIM * C_DIM, x, b2 + l * C_DIM, x,
            M_ROWS, C_DIM, FF_DIM, 0);
    }

    // final LN + tied-embedding logits: (2048,1024) @ (32000,1024)^T
    k_ln<<<M_ROWS, 256>>>(x, lnf_s, lnf_b, h);
    sgemm<1><<<dim3(V_SZ / 128, M_ROWS / 128), 256>>>(
        h, tok, out, nullptr, nullptr, M_ROWS, V_SZ, C_DIM, 0);
}

// round 3
// speedup vs baseline: 2.9869x; 2.9869x over previous
#include <cuda_runtime.h>
#include <cstdint>
#include <math.h>

// ---------------- model constants ----------------
#define C_DIM   1024
#define H_NUM   16
#define D_HEAD  64
#define L_NUM   8
#define T_SEQ   1024
#define B_SZ    2
#define M_ROWS  (B_SZ * T_SEQ)      // 2048
#define FF_DIM  4096
#define V_SZ    32000

// ---------------- device scratch ----------------
__device__ __align__(256) float g_x   [M_ROWS * C_DIM];
__device__ __align__(256) float g_h   [M_ROWS * C_DIM];
__device__ __align__(256) float g_qkv [M_ROWS * 3 * C_DIM];
__device__ __align__(256) float g_ff  [M_ROWS * FF_DIM];
__device__ __align__(256) float g_wp  [3 * C_DIM * C_DIM];   // packed qkv weights [3C, C]
__device__ __align__(256) float g_wt  [FF_DIM * C_DIM];      // transposed weight scratch [N, K]

// ============================================================
// helpers
// ============================================================
__device__ __forceinline__ uint32_t smem_u32(const void* p) {
    uint32_t a;
    asm("{ .reg .u64 t; cvta.to.shared.u64 t, %1; cvt.u32.u64 %0, t; }" : "=r"(a) : "l"(p));
    return a;
}
__device__ __forceinline__ void cpa16(uint32_t dst, const float* src) {
    asm volatile("cp.async.cg.shared.global [%0], [%1], 16;" :: "r"(dst), "l"(src));
}
__device__ __forceinline__ uint32_t f2tf32(float x) {
    uint32_t r;
    asm("cvt.rna.tf32.f32 %0, %1;" : "=r"(r) : "f"(x));
    return r;
}
__device__ __forceinline__ void mma_tf32(float& c0, float& c1, float& c2, float& c3,
                                         uint32_t a0, uint32_t a1, uint32_t a2, uint32_t a3,
                                         uint32_t b0, uint32_t b1) {
    asm volatile("mma.sync.aligned.m16n8k8.row.col.f32.tf32.tf32.f32 "
        "{%0,%1,%2,%3}, {%4,%5,%6,%7}, {%8,%9}, {%0,%1,%2,%3};"
        : "+f"(c0), "+f"(c1), "+f"(c2), "+f"(c3)
        : "r"(a0), "r"(a1), "r"(a2), "r"(a3), "r"(b0), "r"(b1));
}

// ============================================================
// TF32 mma.sync GEMM: C[M, N] = A[M, K] @ B^T   (B stored [N, K] K-major)
// CTA tile 128x128, BK=32, 3-stage cp.async pipeline, 8 warps (2x4), warp tile 64x32.
// ============================================================
#define BK          32
#define ROW_F       36                      // 32 + 4 pad floats
#define TILE_F      (128 * ROW_F)           // 4608 floats per matrix per stage
#define STAGE_F     (2 * TILE_F)            // A then B
#define STAGES      3
#define GSM_BYTES   (STAGES * STAGE_F * 4)  // 110592

__global__ __launch_bounds__(256)
void tgemm(const float* __restrict__ A, const float* __restrict__ B,
           float* __restrict__ Cmat, const float* __restrict__ bias,
           const float* __restrict__ res, int N, int K, int relu)
{
    extern __shared__ float smf[];
    uint32_t sbase = smem_u32(smf);
    int tid  = threadIdx.x;
    int wid  = tid >> 5;
    int lane = tid & 31;
    int wm   = wid >> 2;          // 0..1
    int wn   = wid & 3;           // 0..3
    int bm = blockIdx.y << 7;
    int bn = blockIdx.x << 7;

    const float* Ag = A + (size_t)bm * K;
    const float* Bg = B + (size_t)bn * K;
    int NC = K >> 5;

    // per-thread load coords (4 float4 per matrix per tile)
    int lr[4], lc[4];
#pragma unroll
    for (int i = 0; i < 4; i++) {
        int id = tid + (i << 8);
        lr[i] = id >> 3;
        lc[i] = (id & 7) << 2;
    }

    float acc[4][4][4];
#pragma unroll
    for (int mf = 0; mf < 4; mf++)
#pragma unroll
        for (int nf = 0; nf < 4; nf++)
#pragma unroll
            for (int k = 0; k < 4; k++) acc[mf][nf][k] = 0.f;

    // ---- prologue: issue tiles 0, 1 ----
#pragma unroll
    for (int pc = 0; pc < 2; pc++) {
        int k0 = pc << 5;
        uint32_t so = sbase + (uint32_t)(pc * STAGE_F) * 4u;
#pragma unroll
        for (int i = 0; i < 4; i++) {
            cpa16(so + ((uint32_t)(lr[i] * ROW_F + lc[i]) << 2),
                  Ag + (size_t)lr[i] * K + k0 + lc[i]);
            cpa16(so + ((uint32_t)(TILE_F + lr[i] * ROW_F + lc[i]) << 2),
                  Bg + (size_t)lr[i] * K + k0 + lc[i]);
        }
        asm volatile("cp.async.commit_group;");
    }

    for (int ch = 0; ch < NC; ch++) {
        asm volatile("cp.async.wait_group 1;");
        __syncthreads();

        // issue tile ch+2 into stage (ch+2)%3  (that stage's compute finished before the barrier)
        if (ch + 2 < NC) {
            int k0 = (ch + 2) << 5;
            uint32_t so = sbase + (uint32_t)(((ch + 2) % 3) * STAGE_F) * 4u;
#pragma unroll
            for (int i = 0; i < 4; i++) {
                cpa16(so + ((uint32_t)(lr[i] * ROW_F + lc[i]) << 2),
                      Ag + (size_t)lr[i] * K + k0 + lc[i]);
                cpa16(so + ((uint32_t)(TILE_F + lr[i] * ROW_F + lc[i]) << 2),
                      Bg + (size_t)lr[i] * K + k0 + lc[i]);
            }
        }
        asm volatile("cp.async.commit_group;");

        // ---- compute stage ch%3 ----
        const float* sA = smf + (ch % 3) * STAGE_F;
        const float* sB = sA + TILE_F;
        int ar = (wm << 6) + (lane >> 2);      // A row base within tile
        int bc = (wn << 5) + (lane >> 2);      // B n base within tile
        int kc = lane & 3;
#pragma unroll
        for (int ks = 0; ks < 4; ks++) {
            int k8 = (ks << 3) + kc;
            uint32_t af[4][4], bf[4][2];
#pragma unroll
            for (int mf = 0; mf < 4; mf++) {
                const float* p = sA + (ar + (mf << 4)) * ROW_F + k8;
                af[mf][0] = f2tf32(p[0]);
                af[mf][1] = f2tf32(p[8 * ROW_F]);
                af[mf][2] = f2tf32(p[4]);
                af[mf][3] = f2tf32(p[8 * ROW_F + 4]);
            }
#pragma unroll
            for (int nf = 0; nf < 4; nf++) {
                const float* p = sB + (bc + (nf << 3)) * ROW_F + k8;
                bf[nf][0] = f2tf32(p[0]);
                bf[nf][1] = f2tf32(p[4]);
            }
#pragma unroll
            for (int mf = 0; mf < 4; mf++)
#pragma unroll
                for (int nf = 0; nf < 4; nf++)
                    mma_tf32(acc[mf][nf][0], acc[mf][nf][1], acc[mf][nf][2], acc[mf][nf][3],
                             af[mf][0], af[mf][1], af[mf][2], af[mf][3],
                             bf[nf][0], bf[nf][1]);
        }
    }

    // ---- epilogue ----
    int row0 = bm + (wm << 6) + (lane >> 2);
    int col0 = bn + (wn << 5) + ((lane & 3) << 1);
#pragma unroll
    for (int mf = 0; mf < 4; mf++) {
#pragma unroll
        for (int half = 0; half < 2; half++) {
            int row = row0 + (mf << 4) + half * 8;
            float* op = Cmat + (size_t)row * N + col0;
            const float* rp = res ? res + (size_t)row * N + col0 : nullptr;
#pragma unroll
            for (int nf = 0; nf < 4; nf++) {
                float2 v;
                v.x = acc[mf][nf][half * 2 + 0];
                v.y = acc[mf][nf][half * 2 + 1];
                int c = (nf << 3);
                if (bias) {
                    v.x += bias[col0 + c];
                    v.y += bias[col0 + c + 1];
                }
                if (relu) { v.x = fmaxf(v.x, 0.f); v.y = fmaxf(v.y, 0.f); }
                if (rp) {
                    float2 r2 = *(const float2*)(rp + c);
                    v.x += r2.x; v.y += r2.y;
                }
                *(float2*)(op + c) = v;
            }
        }
    }
}

// ---------------- embedding ----------------
__global__ void k_embed(const int* __restrict__ idx,
                        const float* __restrict__ tok,
                        const float* __restrict__ pos,
                        float* __restrict__ x)
{
    int m = blockIdx.x;
    int c = threadIdx.x * 4;
    int t = m & (T_SEQ - 1);
    int v = idx[m];
    float4 a = *(const float4*)(tok + (size_t)v * C_DIM + c);
    float4 p = *(const float4*)(pos + (size_t)t * C_DIM + c);
    a.x += p.x; a.y += p.y; a.z += p.z; a.w += p.w;
    *(float4*)(x + (size_t)m * C_DIM + c) = a;
}

// ---------------- layernorm ----------------
__global__ void k_ln(const float* __restrict__ x,
                     const float* __restrict__ sc,
                     const float* __restrict__ bi,
                     float* __restrict__ out)
{
    int m = blockIdx.x;
    int tid = threadIdx.x;                 // 256 threads
    int c = tid * 4;
    float4 v = *(const float4*)(x + (size_t)m * C_DIM + c);
    float s = v.x + v.y + v.z + v.w;
    float q = v.x*v.x + v.y*v.y + v.z*v.z + v.w*v.w;

    __shared__ float rs[8], rq[8];
#pragma unroll
    for (int o = 16; o > 0; o >>= 1) {
        s += __shfl_xor_sync(0xffffffffu, s, o);
        q += __shfl_xor_sync(0xffffffffu, q, o);
    }
    if ((tid & 31) == 0) { rs[tid >> 5] = s; rq[tid >> 5] = q; }
    __syncthreads();
    float sum = 0.f, sq = 0.f;
#pragma unroll
    for (int w = 0; w < 8; w++) { sum += rs[w]; sq += rq[w]; }

    float mu = sum * (1.0f / C_DIM);
    float var = sq * (1.0f / C_DIM) - mu * mu;
    float rstd = rsqrtf(var + 1e-5f);

    float4 svv = *(const float4*)(sc + c);
    float4 bvv = *(const float4*)(bi + c);
    float4 o;
    o.x = (v.x - mu) * rstd * svv.x + bvv.x;
    o.y = (v.y - mu) * rstd * svv.y + bvv.y;
    o.z = (v.z - mu) * rstd * svv.z + bvv.z;
    o.w = (v.w - mu) * rstd * svv.w + bvv.w;
    *(float4*)(out + (size_t)m * C_DIM + c) = o;
}

// ---------------- pack qkv weights (L,H,C,D) -> [3C rows, C cols] K-major ----------------
__global__ __launch_bounds__(256)
void k_packT(const float* __restrict__ Wq, const float* __restrict__ Wk,
             const float* __restrict__ Wv, float* __restrict__ out, int l)
{
    __shared__ float t[32][65];
    int b  = blockIdx.x;
    int kb = b & 31;            // k0 / 32
    int hh = (b >> 5) & 15;
    int s  = b >> 9;
    const float* W = (s == 0) ? Wq : ((s == 1) ? Wk : Wv);
    const float* Wb = W + ((size_t)l * H_NUM + hh) * C_DIM * D_HEAD + (size_t)(kb << 5) * D_HEAD;
    int tid = threadIdx.x;
#pragma unroll
    for (int i = 0; i < 8; i++) {
        int idx = tid + (i << 8);
        int r = idx >> 6, d = idx & 63;
        t[r][d] = Wb[(size_t)r * D_HEAD + d];
    }
    __syncthreads();
    int n0 = s * 1024 + hh * 64;
#pragma unroll
    for (int i = 0; i < 8; i++) {
        int idx = tid + (i << 8);
        int d = idx >> 5, kk = idx & 31;
        out[(size_t)(n0 + d) * C_DIM + (kb << 5) + kk] = t[kk][d];
    }
}

// ---------------- weight transpose [K,N] -> [N,K] ----------------
__global__ __launch_bounds__(256)
void k_transpose(const float* __restrict__ in, float* __restrict__ out, int K, int N)
{
    __shared__ float t[32][33];
    int n0 = blockIdx.x << 5;
    int k0 = blockIdx.y << 5;
    int c = threadIdx.x & 31, r = threadIdx.x >> 5;
#pragma unroll
    for (int i = 0; i < 4; i++)
        t[r + i * 8][c] = in[(size_t)(k0 + r + i * 8) * N + n0 + c];
    __syncthreads();
#pragma unroll
    for (int i = 0; i < 4; i++)
        out[(size_t)(n0 + r + i * 8) * K + k0 + c] = t[c][r + i * 8];
}

// ---------------- causal flash attention ----------------
__global__ __launch_bounds__(256)
void k_attn(const float* __restrict__ qkv, float* __restrict__ outb)
{
    __shared__ float qs[64][64];
    __shared__ float ks[32][65];
    __shared__ float vs[32][65];
    __shared__ float ps[64][33];

    int qt  = blockIdx.x;
    int b   = blockIdx.y >> 4;
    int hh  = blockIdx.y & 15;
    int tid = threadIdx.x;
    int tx  = tid & 15, ty = tid >> 4;

    const float* qbase = qkv + (size_t)(b * T_SEQ + qt * 64) * 3072 + hh * 64;
#pragma unroll
    for (int e = 0; e < 16; e++) {
        int i = tid + e * 256;
        int r = i >> 6, d = i & 63;
        qs[r][d] = qbase[(size_t)r * 3072 + d] * 0.125f;
    }

    float m_r[4], l_r[4], oa[4][4];
#pragma unroll
    for (int i = 0; i < 4; i++) {
        m_r[i] = -1e30f; l_r[i] = 0.f;
#pragma unroll
        for (int j = 0; j < 4; j++) oa[i][j] = 0.f;
    }

    const float* kb = qkv + (size_t)(b * T_SEQ) * 3072 + 1024 + hh * 64;
    const float* vb = qkv + (size_t)(b * T_SEQ) * 3072 + 2048 + hh * 64;

    int nkt = 2 * qt + 2;
    for (int kt = 0; kt < nkt; kt++) {
        __syncthreads();
#pragma unroll
        for (int e = 0; e < 8; e++) {
            int i = tid + e * 256;
            int r = i >> 6, d = i & 63;
            ks[r][d] = kb[(size_t)(kt * 32 + r) * 3072 + d];
            vs[r][d] = vb[(size_t)(kt * 32 + r) * 3072 + d];
        }
        __syncthreads();

        float sv[4][2];
#pragma unroll
        for (int i = 0; i < 4; i++) { sv[i][0] = 0.f; sv[i][1] = 0.f; }
#pragma unroll 8
        for (int d = 0; d < 64; d++) {
            float b0 = ks[2 * tx + 0][d];
            float b1 = ks[2 * tx + 1][d];
#pragma unroll
            for (int i = 0; i < 4; i++) {
                float a = qs[4 * ty + i][d];
                sv[i][0] += a * b0;
                sv[i][1] += a * b1;
            }
        }

        if (kt >= 2 * qt) {
#pragma unroll
            for (int i = 0; i < 4; i++)
#pragma unroll
                for (int j = 0; j < 2; j++) {
                    int sg = kt * 32 + 2 * tx + j;
                    int tg = qt * 64 + 4 * ty + i;
                    if (sg > tg) sv[i][j] = -1e30f;
                }
        }

#pragma unroll
        for (int i = 0; i < 4; i++) {
            float mloc = fmaxf(sv[i][0], sv[i][1]);
#pragma unroll
            for (int o = 8; o > 0; o >>= 1)
                mloc = fmaxf(mloc, __shfl_xor_sync(0xffffffffu, mloc, o));
            float mnew = fmaxf(m_r[i], mloc);
            float p0 = expf(sv[i][0] - mnew);
            float p1 = expf(sv[i][1] - mnew);
            float corr = expf(m_r[i] - mnew);
            float rsum = p0 + p1;
#pragma unroll
            for (int o = 8; o > 0; o >>= 1)
                rsum += __shfl_xor_sync(0xffffffffu, rsum, o);
            l_r[i] = l_r[i] * corr + rsum;
            m_r[i] = mnew;
            oa[i][0] *= corr; oa[i][1] *= corr; oa[i][2] *= corr; oa[i][3] *= corr;
            ps[4 * ty + i][2 * tx + 0] = p0;
            ps[4 * ty + i][2 * tx + 1] = p1;
        }
        __syncthreads();

#pragma unroll 4
        for (int s = 0; s < 32; s++) {
            float b0 = vs[s][4 * tx + 0];
            float b1 = vs[s][4 * tx + 1];
            float b2 = vs[s][4 * tx + 2];
            float b3 = vs[s][4 * tx + 3];
#pragma unroll
            for (int i = 0; i < 4; i++) {
                float a = ps[4 * ty + i][s];
                oa[i][0] += a * b0;
                oa[i][1] += a * b1;
                oa[i][2] += a * b2;
                oa[i][3] += a * b3;
            }
        }
    }

    float* ob = outb + (size_t)(b * T_SEQ + qt * 64) * C_DIM + hh * 64;
#pragma unroll
    for (int i = 0; i < 4; i++) {
        float inv = 1.0f / l_r[i];
#pragma unroll
        for (int j = 0; j < 4; j++)
            ob[(size_t)(4 * ty + i) * C_DIM + 4 * tx + j] = oa[i][j] * inv;
    }
}

// ---------------- launcher ----------------
extern "C" void kernel_launch(void* const* d_in, const int* in_sizes, int n_in,
                              void* d_out, int out_size)
{
    const int*   idx    = (const int*)  d_in[0];
    const float* tok    = (const float*)d_in[1];
    const float* pos    = (const float*)d_in[2];
    const float* ln1_s  = (const float*)d_in[3];
    const float* ln1_b  = (const float*)d_in[4];
    const float* Wq     = (const float*)d_in[5];
    const float* Wk     = (const float*)d_in[6];
    const float* Wv     = (const float*)d_in[7];
    const float* Wo     = (const float*)d_in[8];
    const float* bo     = (const float*)d_in[9];
    const float* ln2_s  = (const float*)d_in[10];
    const float* ln2_b  = (const float*)d_in[11];
    const float* W1     = (const float*)d_in[12];
    const float* b1     = (const float*)d_in[13];
    const float* W2     = (const float*)d_in[14];
    const float* b2     = (const float*)d_in[15];
    const float* lnf_s  = (const float*)d_in[16];
    const float* lnf_b  = (const float*)d_in[17];
    float* out = (float*)d_out;

    float *x, *h, *qkv, *ff, *wp, *wt;
    cudaGetSymbolAddress((void**)&x,   g_x);
    cudaGetSymbolAddress((void**)&h,   g_h);
    cudaGetSymbolAddress((void**)&qkv, g_qkv);
    cudaGetSymbolAddress((void**)&ff,  g_ff);
    cudaGetSymbolAddress((void**)&wp,  g_wp);
    cudaGetSymbolAddress((void**)&wt,  g_wt);

    cudaFuncSetAttribute(tgemm, cudaFuncAttributeMaxDynamicSharedMemorySize, GSM_BYTES);

    k_embed<<<M_ROWS, 256>>>(idx, tok, pos, x);

    for (int l = 0; l < L_NUM; l++) {
        // LN1
        k_ln<<<M_ROWS, 256>>>(x, ln1_s + l * C_DIM, ln1_b + l * C_DIM, h);
        // pack qkv weights (transposed, K-major) for this layer
        k_packT<<<3 * 16 * 32, 256>>>(Wq, Wk, Wv, wp, l);
        // fused qkv GEMM: (2048,3072) = h @ wp^T
        tgemm<<<dim3(3072 / 128, M_ROWS / 128), 256, GSM_BYTES>>>(
            h, wp, qkv, nullptr, nullptr, 3072, C_DIM, 0);
        // attention -> h
        k_attn<<<dim3(T_SEQ / 64, B_SZ * H_NUM), 256>>>(qkv, h);
        // x = x + h @ Wo + bo
        k_transpose<<<dim3(C_DIM / 32, C_DIM / 32), 256>>>(
            Wo + (size_t)l * C_DIM * C_DIM, wt, C_DIM, C_DIM);
        tgemm<<<dim3(C_DIM / 128, M_ROWS / 128), 256, GSM_BYTES>>>(
            h, wt, x, bo + l * C_DIM, x, C_DIM, C_DIM, 0);
        // LN2
        k_ln<<<M_ROWS, 256>>>(x, ln2_s + l * C_DIM, ln2_b + l * C_DIM, h);
        // ff = relu(h @ W1 + b1)
        k_transpose<<<dim3(FF_DIM / 32, C_DIM / 32), 256>>>(
            W1 + (size_t)l * C_DIM * FF_DIM, wt, C_DIM, FF_DIM);
        tgemm<<<dim3(FF_DIM / 128, M_ROWS / 128), 256, GSM_BYTES>>>(
            h, wt, ff, b1 + l * FF_DIM, nullptr, FF_DIM, C_DIM, 1);
        // x = x + ff @ W2 + b2
        k_transpose<<<dim3(C_DIM / 32, FF_DIM / 32), 256>>>(
            W2 + (size_t)l * FF_DIM * C_DIM, wt, FF_DIM, C_DIM);
        tgemm<<<dim3(C_DIM / 128, M_ROWS / 128), 256, GSM_BYTES>>>(
            ff, wt, x, b2 + l * C_DIM, x, C_DIM, FF_DIM, 0);
    }

    // final LN + tied-embedding logits: (2048,32000) = h @ tok^T (tok is [V,K])
    k_ln<<<M_ROWS, 256>>>(x, lnf_s, lnf_b, h);
    tgemm<<<dim3(V_SZ / 128, M_ROWS / 128), 256, GSM_BYTES>>>(
        h, tok, out, nullptr, nullptr, V_SZ, C_DIM, 0);
}

// round 4
// speedup vs baseline: 3.2043x; 1.0728x over previous
#include <cuda_runtime.h>
#include <cstdint>
#include <math.h>

// ---------------- model constants ----------------
#define C_DIM   1024
#define H_NUM   16
#define D_HEAD  64
#define L_NUM   8
#define T_SEQ   1024
#define B_SZ    2
#define M_ROWS  (B_SZ * T_SEQ)      // 2048
#define FF_DIM  4096
#define V_SZ    32000

// ---------------- device scratch ----------------
__device__ __align__(256) float g_x   [M_ROWS * C_DIM];
__device__ __align__(256) float g_h   [M_ROWS * C_DIM];
__device__ __align__(256) float g_qkv [M_ROWS * 3 * C_DIM];
__device__ __align__(256) float g_ff  [M_ROWS * FF_DIM];
__device__ __align__(256) float g_wp  [3 * C_DIM * C_DIM];   // packed qkv weights [3C, C]
__device__ __align__(256) float g_wt  [FF_DIM * C_DIM];      // transposed weight scratch [N, K]

// ============================================================
// helpers
// ============================================================
__device__ __forceinline__ uint32_t smem_u32(const void* p) {
    uint32_t a;
    asm("{ .reg .u64 t; cvta.to.shared.u64 t, %1; cvt.u32.u64 %0, t; }" : "=r"(a) : "l"(p));
    return a;
}
__device__ __forceinline__ void cpa16(uint32_t dst, const float* src) {
    asm volatile("cp.async.cg.shared.global [%0], [%1], 16;" :: "r"(dst), "l"(src));
}
__device__ __forceinline__ uint32_t f2tf32(float x) {
    uint32_t r;
    asm("cvt.rna.tf32.f32 %0, %1;" : "=r"(r) : "f"(x));
    return r;
}
__device__ __forceinline__ float tf32r(float x) {       // round-to-tf32, as float
    return __uint_as_float(f2tf32(x));
}
__device__ __forceinline__ void mma_tf32(float& c0, float& c1, float& c2, float& c3,
                                         uint32_t a0, uint32_t a1, uint32_t a2, uint32_t a3,
                                         uint32_t b0, uint32_t b1) {
    asm volatile("mma.sync.aligned.m16n8k8.row.col.f32.tf32.tf32.f32 "
        "{%0,%1,%2,%3}, {%4,%5,%6,%7}, {%8,%9}, {%0,%1,%2,%3};"
        : "+f"(c0), "+f"(c1), "+f"(c2), "+f"(c3)
        : "r"(a0), "r"(a1), "r"(a2), "r"(a3), "r"(b0), "r"(b1));
}

// ============================================================
// TF32 mma.sync GEMM: C[M, N] = A[M, K] @ B^T   (B stored [N, K] K-major)
// CTA tile 128x128, BK=32, 2-stage cp.async double buffer, 8 warps (2x4),
// warp tile 64x32. Operands pre-rounded to TF32 (CVT_B=1 adds runtime cvt on B).
// ============================================================
#define BK          32
#define ROW_F       36                      // 32 + 4 pad floats (conflict-free frag LDS)
#define TILE_F      (128 * ROW_F)           // 4608 floats per matrix per stage
#define STAGE_F     (2 * TILE_F)            // A then B
#define GSM_BYTES   (2 * STAGE_F * 4)       // 73728 bytes -> 2 CTAs/SM

template<int CVT_B>
__global__ __launch_bounds__(256, 2)
void tgemm(const float* __restrict__ A, const float* __restrict__ B,
           float* __restrict__ Cmat, const float* __restrict__ bias,
           const float* __restrict__ res, int N, int K, int relu)
{
    extern __shared__ float smf[];
    uint32_t sbase = smem_u32(smf);
    int tid  = threadIdx.x;
    int wid  = tid >> 5;
    int lane = tid & 31;
    int wm   = wid >> 2;          // 0..1
    int wn   = wid & 3;           // 0..3
    int bm = blockIdx.y << 7;
    int bn = blockIdx.x << 7;

    const float* Ag = A + (size_t)bm * K;
    const float* Bg = B + (size_t)bn * K;
    int NC = K >> 5;

    // per-thread load coords (4 float4 per matrix per tile)
    int lr[4], lc[4];
#pragma unroll
    for (int i = 0; i < 4; i++) {
        int id = tid + (i << 8);
        lr[i] = id >> 3;
        lc[i] = (id & 7) << 2;
    }

    float acc[4][4][4];
#pragma unroll
    for (int mf = 0; mf < 4; mf++)
#pragma unroll
        for (int nf = 0; nf < 4; nf++)
#pragma unroll
            for (int k = 0; k < 4; k++) acc[mf][nf][k] = 0.f;

    // ---- prologue: issue tile 0 into stage 0 ----
#pragma unroll
    for (int i = 0; i < 4; i++) {
        cpa16(sbase + ((uint32_t)(lr[i] * ROW_F + lc[i]) << 2),
              Ag + (size_t)lr[i] * K + lc[i]);
        cpa16(sbase + ((uint32_t)(TILE_F + lr[i] * ROW_F + lc[i]) << 2),
              Bg + (size_t)lr[i] * K + lc[i]);
    }
    asm volatile("cp.async.commit_group;");

    for (int ch = 0; ch < NC; ch++) {
        if (ch > 0) __syncthreads();      // stage (ch+1)&1 free of readers
        if (ch + 1 < NC) {
            int k0 = (ch + 1) << 5;
            uint32_t so = sbase + (uint32_t)(((ch + 1) & 1) * STAGE_F) * 4u;
#pragma unroll
            for (int i = 0; i < 4; i++) {
                cpa16(so + ((uint32_t)(lr[i] * ROW_F + lc[i]) << 2),
                      Ag + (size_t)lr[i] * K + k0 + lc[i]);
                cpa16(so + ((uint32_t)(TILE_F + lr[i] * ROW_F + lc[i]) << 2),
                      Bg + (size_t)lr[i] * K + k0 + lc[i]);
            }
        }
        asm volatile("cp.async.commit_group;");
        asm volatile("cp.async.wait_group 1;");   // tile ch resident
        __syncthreads();

        // ---- compute stage ch&1 ----
        const float* sA = smf + (ch & 1) * STAGE_F;
        const float* sB = sA + TILE_F;
        int ar = (wm << 6) + (lane >> 2);
        int bc = (wn << 5) + (lane >> 2);
        int kc = lane & 3;
#pragma unroll
        for (int ks = 0; ks < 4; ks++) {
            int k8 = (ks << 3) + kc;
            uint32_t af[4][4], bf[4][2];
#pragma unroll
            for (int mf = 0; mf < 4; mf++) {
                const float* p = sA + (ar + (mf << 4)) * ROW_F + k8;
                af[mf][0] = __float_as_uint(p[0]);
                af[mf][1] = __float_as_uint(p[8 * ROW_F]);
                af[mf][2] = __float_as_uint(p[4]);
                af[mf][3] = __float_as_uint(p[8 * ROW_F + 4]);
            }
#pragma unroll
            for (int nf = 0; nf < 4; nf++) {
                const float* p = sB + (bc + (nf << 3)) * ROW_F + k8;
                if (CVT_B) {
                    bf[nf][0] = f2tf32(p[0]);
                    bf[nf][1] = f2tf32(p[4]);
                } else {
                    bf[nf][0] = __float_as_uint(p[0]);
                    bf[nf][1] = __float_as_uint(p[4]);
                }
            }
#pragma unroll
            for (int mf = 0; mf < 4; mf++)
#pragma unroll
                for (int nf = 0; nf < 4; nf++)
                    mma_tf32(acc[mf][nf][0], acc[mf][nf][1], acc[mf][nf][2], acc[mf][nf][3],
                             af[mf][0], af[mf][1], af[mf][2], af[mf][3],
                             bf[nf][0], bf[nf][1]);
        }
    }

    // ---- epilogue ----
    int row0 = bm + (wm << 6) + (lane >> 2);
    int col0 = bn + (wn << 5) + ((lane & 3) << 1);
#pragma unroll
    for (int mf = 0; mf < 4; mf++) {
#pragma unroll
        for (int half = 0; half < 2; half++) {
            int row = row0 + (mf << 4) + half * 8;
            float* op = Cmat + (size_t)row * N + col0;
            const float* rp = res ? res + (size_t)row * N + col0 : nullptr;
#pragma unroll
            for (int nf = 0; nf < 4; nf++) {
                float2 v;
                v.x = acc[mf][nf][half * 2 + 0];
                v.y = acc[mf][nf][half * 2 + 1];
                int c = (nf << 3);
                if (bias) {
                    v.x += bias[col0 + c];
                    v.y += bias[col0 + c + 1];
                }
                if (relu) {   // relu outputs feed the next GEMM's A: pre-round to TF32
                    v.x = tf32r(fmaxf(v.x, 0.f));
                    v.y = tf32r(fmaxf(v.y, 0.f));
                }
                if (rp) {
                    float2 r2 = *(const float2*)(rp + c);
                    v.x += r2.x; v.y += r2.y;
                }
                *(float2*)(op + c) = v;
            }
        }
    }
}

// ---------------- embedding ----------------
__global__ void k_embed(const int* __restrict__ idx,
                        const float* __restrict__ tok,
                        const float* __restrict__ pos,
                        float* __restrict__ x)
{
    int m = blockIdx.x;
    int c = threadIdx.x * 4;
    int t = m & (T_SEQ - 1);
    int v = idx[m];
    float4 a = *(const float4*)(tok + (size_t)v * C_DIM + c);
    float4 p = *(const float4*)(pos + (size_t)t * C_DIM + c);
    a.x += p.x; a.y += p.y; a.z += p.z; a.w += p.w;
    *(float4*)(x + (size_t)m * C_DIM + c) = a;
}

// ---------------- layernorm (outputs pre-rounded to TF32: consumed only by GEMM A) ----------------
__global__ void k_ln(const float* __restrict__ x,
                     const float* __restrict__ sc,
                     const float* __restrict__ bi,
                     float* __restrict__ out)
{
    int m = blockIdx.x;
    int tid = threadIdx.x;                 // 256 threads
    int c = tid * 4;
    float4 v = *(const float4*)(x + (size_t)m * C_DIM + c);
    float s = v.x + v.y + v.z + v.w;
    float q = v.x*v.x + v.y*v.y + v.z*v.z + v.w*v.w;

    __shared__ float rs[8], rq[8];
#pragma unroll
    for (int o = 16; o > 0; o >>= 1) {
        s += __shfl_xor_sync(0xffffffffu, s, o);
        q += __shfl_xor_sync(0xffffffffu, q, o);
    }
    if ((tid & 31) == 0) { rs[tid >> 5] = s; rq[tid >> 5] = q; }
    __syncthreads();
    float sum = 0.f, sq = 0.f;
#pragma unroll
    for (int w = 0; w < 8; w++) { sum += rs[w]; sq += rq[w]; }

    float mu = sum * (1.0f / C_DIM);
    float var = sq * (1.0f / C_DIM) - mu * mu;
    float rstd = rsqrtf(var + 1e-5f);

    float4 svv = *(const float4*)(sc + c);
    float4 bvv = *(const float4*)(bi + c);
    float4 o;
    o.x = tf32r((v.x - mu) * rstd * svv.x + bvv.x);
    o.y = tf32r((v.y - mu) * rstd * svv.y + bvv.y);
    o.z = tf32r((v.z - mu) * rstd * svv.z + bvv.z);
    o.w = tf32r((v.w - mu) * rstd * svv.w + bvv.w);
    *(float4*)(out + (size_t)m * C_DIM + c) = o;
}

// ---------------- pack qkv weights (L,H,C,D) -> [3C, C] K-major (TF32 pre-rounded) ----------------
__global__ __launch_bounds__(256)
void k_packT(const float* __restrict__ Wq, const float* __restrict__ Wk,
             const float* __restrict__ Wv, float* __restrict__ out, int l)
{
    __shared__ float t[32][65];
    int b  = blockIdx.x;
    int kb = b & 31;            // k0 / 32
    int hh = (b >> 5) & 15;
    int s  = b >> 9;
    const float* W = (s == 0) ? Wq : ((s == 1) ? Wk : Wv);
    const float* Wb = W + ((size_t)l * H_NUM + hh) * C_DIM * D_HEAD + (size_t)(kb << 5) * D_HEAD;
    int tid = threadIdx.x;
#pragma unroll
    for (int i = 0; i < 8; i++) {
        int idx = tid + (i << 8);
        int r = idx >> 6, d = idx & 63;
        t[r][d] = Wb[(size_t)r * D_HEAD + d];
    }
    __syncthreads();
    int n0 = s * 1024 + hh * 64;
#pragma unroll
    for (int i = 0; i < 8; i++) {
        int idx = tid + (i << 8);
        int d = idx >> 5, kk = idx & 31;
        out[(size_t)(n0 + d) * C_DIM + (kb << 5) + kk] = tf32r(t[kk][d]);
    }
}

// ---------------- weight transpose [K,N] -> [N,K] (TF32 pre-rounded) ----------------
__global__ __launch_bounds__(256)
void k_transpose(const float* __restrict__ in, float* __restrict__ out, int K, int N)
{
    __shared__ float t[32][33];
    int n0 = blockIdx.x << 5;
    int k0 = blockIdx.y << 5;
    int c = threadIdx.x & 31, r = threadIdx.x >> 5;
#pragma unroll
    for (int i = 0; i < 4; i++)
        t[r + i * 8][c] = in[(size_t)(k0 + r + i * 8) * N + n0 + c];
    __syncthreads();
#pragma unroll
    for (int i = 0; i < 4; i++)
        out[(size_t)(n0 + r + i * 8) * K + k0 + c] = tf32r(t[c][r + i * 8]);
}

// ---------------- causal flash attention (output pre-rounded: feeds Wo GEMM A) -----
__global__ __launch_bounds__(256)
void k_attn(const float* __restrict__ qkv, float* __restrict__ outb)
{
    __shared__ float qs[64][64];
    __shared__ float ks[32][65];
    __shared__ float vs[32][65];
    __shared__ float ps[64][33];

    int qt  = blockIdx.x;
    int b   = blockIdx.y >> 4;
    int hh  = blockIdx.y & 15;
    int tid = threadIdx.x;
    int tx  = tid & 15, ty = tid >> 4;

    const float* qbase = qkv + (size_t)(b * T_SEQ + qt * 64) * 3072 + hh * 64;
#pragma unroll
    for (int e = 0; e < 16; e++) {
        int i = tid + e * 256;
        int r = i >> 6, d = i & 63;
        qs[r][d] = qbase[(size_t)r * 3072 + d] * 0.125f;
    }

    float m_r[4], l_r[4], oa[4][4];
#pragma unroll
    for (int i = 0; i < 4; i++) {
        m_r[i] = -1e30f; l_r[i] = 0.f;
#pragma unroll
        for (int j = 0; j < 4; j++) oa[i][j] = 0.f;
    }

    const float* kb = qkv + (size_t)(b * T_SEQ) * 3072 + 1024 + hh * 64;
    const float* vb = qkv + (size_t)(b * T_SEQ) * 3072 + 2048 + hh * 64;

    int nkt = 2 * qt + 2;
    for (int kt = 0; kt < nkt; kt++) {
        __syncthreads();
#pragma unroll
        for (int e = 0; e < 8; e++) {
            int i = tid + e * 256;
            int r = i >> 6, d = i & 63;
            ks[r][d] = kb[(size_t)(kt * 32 + r) * 3072 + d];
            vs[r][d] = vb[(size_t)(kt * 32 + r) * 3072 + d];
        }
        __syncthreads();

        float sv[4][2];
#pragma unroll
        for (int i = 0; i < 4; i++) { sv[i][0] = 0.f; sv[i][1] = 0.f; }
#pragma unroll 8
        for (int d = 0; d < 64; d++) {
            float b0 = ks[2 * tx + 0][d];
            float b1 = ks[2 * tx + 1][d];
#pragma unroll
            for (int i = 0; i < 4; i++) {
                float a = qs[4 * ty + i][d];
                sv[i][0] += a * b0;
                sv[i][1] += a * b1;
            }
        }

        if (kt >= 2 * qt) {
#pragma unroll
            for (int i = 0; i < 4; i++)
#pragma unroll
                for (int j = 0; j < 2; j++) {
                    int sg = kt * 32 + 2 * tx + j;
                    int tg = qt * 64 + 4 * ty + i;
                    if (sg > tg) sv[i][j] = -1e30f;
                }
        }

#pragma unroll
        for (int i = 0; i < 4; i++) {
            float mloc = fmaxf(sv[i][0], sv[i][1]);
#pragma unroll
            for (int o = 8; o > 0; o >>= 1)
                mloc = fmaxf(mloc, __shfl_xor_sync(0xffffffffu, mloc, o));
            float mnew = fmaxf(m_r[i], mloc);
            float p0 = expf(sv[i][0] - mnew);
            float p1 = expf(sv[i][1] - mnew);
            float corr = expf(m_r[i] - mnew);
            float rsum = p0 + p1;
#pragma unroll
            for (int o = 8; o > 0; o >>= 1)
                rsum += __shfl_xor_sync(0xffffffffu, rsum, o);
            l_r[i] = l_r[i] * corr + rsum;
            m_r[i] = mnew;
            oa[i][0] *= corr; oa[i][1] *= corr; oa[i][2] *= corr; oa[i][3] *= corr;
            ps[4 * ty + i][2 * tx + 0] = p0;
            ps[4 * ty + i][2 * tx + 1] = p1;
        }
        __syncthreads();

#pragma unroll 4
        for (int s = 0; s < 32; s++) {
            float b0 = vs[s][4 * tx + 0];
            float b1 = vs[s][4 * tx + 1];
            float b2 = vs[s][4 * tx + 2];
            float b3 = vs[s][4 * tx + 3];
#pragma unroll
            for (int i = 0; i < 4; i++) {
                float a = ps[4 * ty + i][s];
                oa[i][0] += a * b0;
                oa[i][1] += a * b1;
                oa[i][2] += a * b2;
                oa[i][3] += a * b3;
            }
        }
    }

    float* ob = outb + (size_t)(b * T_SEQ + qt * 64) * C_DIM + hh * 64;
#pragma unroll
    for (int i = 0; i < 4; i++) {
        float inv = 1.0f / l_r[i];
#pragma unroll
        for (int j = 0; j < 4; j++)
            ob[(size_t)(4 * ty + i) * C_DIM + 4 * tx + j] = tf32r(oa[i][j] * inv);
    }
}

// ---------------- launcher ----------------
extern "C" void kernel_launch(void* const* d_in, const int* in_sizes, int n_in,
                              void* d_out, int out_size)
{
    const int*   idx    = (const int*)  d_in[0];
    const float* tok    = (const float*)d_in[1];
    const float* pos    = (const float*)d_in[2];
    const float* ln1_s  = (const float*)d_in[3];
    const float* ln1_b  = (const float*)d_in[4];
    const float* Wq     = (const float*)d_in[5];
    const float* Wk     = (const float*)d_in[6];
    const float* Wv     = (const float*)d_in[7];
    const float* Wo     = (const float*)d_in[8];
    const float* bo     = (const float*)d_in[9];
    const float* ln2_s  = (const float*)d_in[10];
    const float* ln2_b  = (const float*)d_in[11];
    const float* W1     = (const float*)d_in[12];
    const float* b1     = (const float*)d_in[13];
    const float* W2     = (const float*)d_in[14];
    const float* b2     = (const float*)d_in[15];
    const float* lnf_s  = (const float*)d_in[16];
    const float* lnf_b  = (const float*)d_in[17];
    float* out = (float*)d_out;

    float *x, *h, *qkv, *ff, *wp, *wt;
    cudaGetSymbolAddress((void**)&x,   g_x);
    cudaGetSymbolAddress((void**)&h,   g_h);
    cudaGetSymbolAddress((void**)&qkv, g_qkv);
    cudaGetSymbolAddress((void**)&ff,  g_ff);
    cudaGetSymbolAddress((void**)&wp,  g_wp);
    cudaGetSymbolAddress((void**)&wt,  g_wt);

    cudaFuncSetAttribute(tgemm<0>, cudaFuncAttributeMaxDynamicSharedMemorySize, GSM_BYTES);
    cudaFuncSetAttribute(tgemm<1>, cudaFuncAttributeMaxDynamicSharedMemorySize, GSM_BYTES);

    k_embed<<<M_ROWS, 256>>>(idx, tok, pos, x);

    for (int l = 0; l < L_NUM; l++) {
        // LN1
        k_ln<<<M_ROWS, 256>>>(x, ln1_s + l * C_DIM, ln1_b + l * C_DIM, h);
        // pack qkv weights (transposed, K-major, TF32) for this layer
        k_packT<<<3 * 16 * 32, 256>>>(Wq, Wk, Wv, wp, l);
        // fused qkv GEMM: (2048,3072) = h @ wp^T
        tgemm<0><<<dim3(3072 / 128, M_ROWS / 128), 256, GSM_BYTES>>>(
            h, wp, qkv, nullptr, nullptr, 3072, C_DIM, 0);
        // attention -> h
        k_attn<<<dim3(T_SEQ / 64, B_SZ * H_NUM), 256>>>(qkv, h);
        // x = x + h @ Wo + bo
        k_transpose<<<dim3(C_DIM / 32, C_DIM / 32), 256>>>(
            Wo + (size_t)l * C_DIM * C_DIM, wt, C_DIM, C_DIM);
        tgemm<0><<<dim3(C_DIM / 128, M_ROWS / 128), 256, GSM_BYTES>>>(
            h, wt, x, bo + l * C_DIM, x, C_DIM, C_DIM, 0);
        // LN2
        k_ln<<<M_ROWS, 256>>>(x, ln2_s + l * C_DIM, ln2_b + l * C_DIM, h);
        // ff = relu(h @ W1 + b1)
        k_transpose<<<dim3(FF_DIM / 32, C_DIM / 32), 256>>>(
            W1 + (size_t)l * C_DIM * FF_DIM, wt, C_DIM, FF_DIM);
        tgemm<0><<<dim3(FF_DIM / 128, M_ROWS / 128), 256, GSM_BYTES>>>(
            h, wt, ff, b1 + l * FF_DIM, nullptr, FF_DIM, C_DIM, 1);
        // x = x + ff @ W2 + b2
        k_transpose<<<dim3(C_DIM / 32, FF_DIM / 32), 256>>>(
            W2 + (size_t)l * FF_DIM * C_DIM, wt, FF_DIM, C_DIM);
        tgemm<0><<<dim3(C_DIM / 128, M_ROWS / 128), 256, GSM_BYTES>>>(
            ff, wt, x, b2 + l * C_DIM, x, C_DIM, FF_DIM, 0);
    }

    // final LN + tied-embedding logits: (2048,32000) = h @ tok^T (tok is [V,K], cvt at load)
    k_ln<<<M_ROWS, 256>>>(x, lnf_s, lnf_b, h);
    tgemm<1><<<dim3(V_SZ / 128, M_ROWS / 128), 256, GSM_BYTES>>>(
        h, tok, out, nullptr, nullptr, V_SZ, C_DIM, 0);
}